// round 3
// baseline (speedup 1.0000x reference)
#include <cuda_runtime.h>

#define N_NODES 100000
#define N_EDGES 1600000
#define D_IN 128
#define D_HID 128
#define D_OUTD 64

// ---------------- scratch (device globals; no allocation) ----------------
__device__ float g_Y1[N_NODES * D_HID];    // X @ W_l1^T
__device__ float g_Z1[N_NODES * D_HID];    // X @ W_r1^T + b1
__device__ float g_AGG1[N_NODES * D_HID];
__device__ float g_H[N_NODES * D_HID];     // layer-1 output (post relu)
__device__ float g_Y2[N_NODES * D_OUTD];   // H @ W_l2^T
__device__ float g_Z2[N_NODES * D_OUTD];   // H @ W_r2^T + b2
__device__ float g_AGG2[N_NODES * D_OUTD];
__device__ int   g_deg[N_NODES];
__device__ int   g_is64;                   // 1 if edge_index is int64, 0 if int32

// ---------------- dtype probe: int64 indices have zero high words ----------
__global__ void detect_kernel(const int* __restrict__ ei) {
    // Examine words 1,3,5,...,255. If edge_index is int64 (little-endian),
    // these are the high halves of indices < N_NODES -> all zero.
    int all_zero = 1;
    for (int i = 0; i < 128; i++) {
        if (ei[2 * i + 1] != 0) { all_zero = 0; break; }
    }
    g_is64 = all_zero;
}

__device__ __forceinline__ int edge_at(const int* ei, int idx, int is64) {
    // idx in [0, 2*N_EDGES): flat index into the logical [2, N_EDGES] array
    return is64 ? (int)((const long long*)ei)[idx] : ei[idx];
}

// ---------------- zero accumulators + degree ----------------
__global__ void zero_kernel() {
    int i = blockIdx.x * blockDim.x + threadIdx.x;
    const float4 z = make_float4(0.f, 0.f, 0.f, 0.f);
    if (i < N_NODES * D_HID / 4)  ((float4*)g_AGG1)[i] = z;
    if (i < N_NODES * D_OUTD / 4) ((float4*)g_AGG2)[i] = z;
    if (i < N_NODES / 4)          ((int4*)g_deg)[i] = make_int4(0, 0, 0, 0);
}

__global__ void deg_kernel(const int* __restrict__ ei) {
    int e = blockIdx.x * blockDim.x + threadIdx.x;
    if (e < N_EDGES) {
        int is64 = g_is64;
        int dst = edge_at(ei, N_EDGES + e, is64);
        if (dst >= 0 && dst < N_NODES) atomicAdd(&g_deg[dst], 1);
    }
}

// ---------------- fused dual GEMM:  Y = X@Wl^T,  Z = X@Wr^T + b ----------------
// C = X[N,128] @ Wcat[2*DOUT,128]^T, tiled TM=64 x TN=64, K chunked by 16.
// blockIdx.y selects a 64-col tile of the concat space; since DOUT is a
// multiple of 64, a tile is entirely in Y or entirely in Z.
template <int LAYER>
__global__ __launch_bounds__(256) void gemm_fused(const float* __restrict__ Xin,
                                                  const float* __restrict__ Wl,
                                                  const float* __restrict__ Wr,
                                                  const float* __restrict__ bias) {
    constexpr int DOUT = (LAYER == 1) ? D_HID : D_OUTD;
    constexpr int K = 128, TM = 64, TN = 64, TK = 16;
    const float* X = (LAYER == 1) ? Xin : g_H;
    float* Y = (LAYER == 1) ? g_Y1 : g_Y2;
    float* Z = (LAYER == 1) ? g_Z1 : g_Z2;

    __shared__ float Xs[TK][TM];
    __shared__ float Ws[TK][TN];

    const int tid = threadIdx.x;      // 256 threads
    const int tx = tid & 15;          // col group
    const int ty = tid >> 4;          // row group
    const int m0 = blockIdx.x * TM;
    const int n0 = blockIdx.y * TN;   // col in concat [0, 2*DOUT)
    const bool isZ = (n0 >= DOUT);
    const float* Wbase = isZ ? Wr : Wl;
    const int ncol0 = isZ ? (n0 - DOUT) : n0;

    // loader mapping: 256 threads -> 64 rows x 4 float4s (16 k-values)
    const int lr = tid >> 2;   // 0..63
    const int lc = tid & 3;    // 0..3
    int mrow = m0 + lr; if (mrow >= N_NODES) mrow = N_NODES - 1;
    const float* xptr = X + (size_t)mrow * K;
    const float* wptr = Wbase + (size_t)(ncol0 + lr) * K;

    float acc[4][4] = {};

    for (int k0 = 0; k0 < K; k0 += TK) {
        float4 xv = *(const float4*)(xptr + k0 + lc * 4);
        float4 wv = *(const float4*)(wptr + k0 + lc * 4);
        Xs[lc * 4 + 0][lr] = xv.x; Xs[lc * 4 + 1][lr] = xv.y;
        Xs[lc * 4 + 2][lr] = xv.z; Xs[lc * 4 + 3][lr] = xv.w;
        Ws[lc * 4 + 0][lr] = wv.x; Ws[lc * 4 + 1][lr] = wv.y;
        Ws[lc * 4 + 2][lr] = wv.z; Ws[lc * 4 + 3][lr] = wv.w;
        __syncthreads();
#pragma unroll
        for (int k = 0; k < TK; k++) {
            float4 a = *(const float4*)&Xs[k][ty * 4];
            float4 w = *(const float4*)&Ws[k][tx * 4];
            acc[0][0] += a.x * w.x; acc[0][1] += a.x * w.y; acc[0][2] += a.x * w.z; acc[0][3] += a.x * w.w;
            acc[1][0] += a.y * w.x; acc[1][1] += a.y * w.y; acc[1][2] += a.y * w.z; acc[1][3] += a.y * w.w;
            acc[2][0] += a.z * w.x; acc[2][1] += a.z * w.y; acc[2][2] += a.z * w.z; acc[2][3] += a.z * w.w;
            acc[3][0] += a.w * w.x; acc[3][1] += a.w * w.y; acc[3][2] += a.w * w.z; acc[3][3] += a.w * w.w;
        }
        __syncthreads();
    }

    float4 bv = make_float4(0.f, 0.f, 0.f, 0.f);
    if (isZ) {
        bv.x = bias[ncol0 + tx * 4 + 0]; bv.y = bias[ncol0 + tx * 4 + 1];
        bv.z = bias[ncol0 + tx * 4 + 2]; bv.w = bias[ncol0 + tx * 4 + 3];
    }
#pragma unroll
    for (int i = 0; i < 4; i++) {
        int m = m0 + ty * 4 + i;
        if (m >= N_NODES) continue;
        float4 r = make_float4(acc[i][0] + bv.x, acc[i][1] + bv.y,
                               acc[i][2] + bv.z, acc[i][3] + bv.w);
        float* dst = (isZ ? Z : Y) + (size_t)m * DOUT + ncol0 + tx * 4;
        *(float4*)dst = r;
    }
}

// ---------------- edge scatter: AGG[dst] += Y[src] (vector red atomics) --------
template <int LAYER>
__global__ void scatter_kernel(const int* __restrict__ ei) {
    constexpr int D = (LAYER == 1) ? D_HID : D_OUTD;
    constexpr int G = D / 4;   // lanes per edge (32 or 16)
    const float* Y = (LAYER == 1) ? g_Y1 : g_Y2;
    float* AGG = (LAYER == 1) ? g_AGG1 : g_AGG2;

    int t = blockIdx.x * blockDim.x + threadIdx.x;
    int e = t / G;
    int lane = t % G;
    if (e >= N_EDGES) return;
    int is64 = g_is64;
    int src = edge_at(ei, e, is64);
    int dst = edge_at(ei, N_EDGES + e, is64);
    if ((unsigned)src >= N_NODES || (unsigned)dst >= N_NODES) return;
    float4 v = *(const float4*)(Y + (size_t)src * D + lane * 4);
    float* p = AGG + (size_t)dst * D + lane * 4;
    asm volatile("red.global.add.v4.f32 [%0], {%1, %2, %3, %4};"
                 :: "l"(p), "f"(v.x), "f"(v.y), "f"(v.z), "f"(v.w)
                 : "memory");
}

// ---------------- combine: O = AGG/max(deg,1) + Z  (+relu layer 1) ------------
template <int LAYER>
__global__ void combine_kernel(float* __restrict__ Out) {
    constexpr int D = (LAYER == 1) ? D_HID : D_OUTD;
    constexpr bool RELU = (LAYER == 1);
    const float* AGG = (LAYER == 1) ? g_AGG1 : g_AGG2;
    const float* Z = (LAYER == 1) ? g_Z1 : g_Z2;
    float* O = (LAYER == 1) ? g_H : Out;

    int i = blockIdx.x * blockDim.x + threadIdx.x;   // over N*D/4
    if (i >= N_NODES * D / 4) return;
    int node = i / (D / 4);
    float inv = 1.0f / fmaxf((float)g_deg[node], 1.0f);
    float4 a = ((const float4*)AGG)[i];
    float4 z = ((const float4*)Z)[i];
    float4 r = make_float4(fmaf(a.x, inv, z.x), fmaf(a.y, inv, z.y),
                           fmaf(a.z, inv, z.z), fmaf(a.w, inv, z.w));
    if (RELU) {
        r.x = fmaxf(r.x, 0.f); r.y = fmaxf(r.y, 0.f);
        r.z = fmaxf(r.z, 0.f); r.w = fmaxf(r.w, 0.f);
    }
    ((float4*)O)[i] = r;
}

// ---------------- launch ----------------
extern "C" void kernel_launch(void* const* d_in, const int* in_sizes, int n_in,
                              void* d_out, int out_size) {
    // Resolve inputs by element count (robust to any metadata permutation
    // that preserves relative order of identically-shaped tensors).
    const float* X = nullptr;        // 12,800,000
    const int*   ei = nullptr;       // 3,200,000 elements (dtype probed on device)
    const float* Wl1 = nullptr, *Wr1 = nullptr;  // 16384 each, in order
    const float* Wl2 = nullptr, *Wr2 = nullptr;  // 8192 each, in order
    const float* b1 = nullptr, *b2 = nullptr;    // 128, 64

    for (int i = 0; i < n_in; i++) {
        int sz = in_sizes[i];
        const void* p = d_in[i];
        if (sz == N_NODES * D_IN)      X = (const float*)p;
        else if (sz == 2 * N_EDGES)    ei = (const int*)p;
        else if (sz == D_HID * D_IN)   { if (!Wl1) Wl1 = (const float*)p; else Wr1 = (const float*)p; }
        else if (sz == D_OUTD * D_HID) { if (!Wl2) Wl2 = (const float*)p; else Wr2 = (const float*)p; }
        else if (sz == D_HID)          b1 = (const float*)p;
        else if (sz == D_OUTD)         b2 = (const float*)p;
    }
    float* out = (float*)d_out;

    const int TPB = 256;

    // -1) dtype probe (1 thread; negligible)
    detect_kernel<<<1, 1>>>(ei);

    // 0) zero accumulators + degrees (largest range: N*D_HID/4 = 3.2M)
    zero_kernel<<<(N_NODES * D_HID / 4 + TPB - 1) / TPB, TPB>>>();

    // 1) degrees
    deg_kernel<<<(N_EDGES + TPB - 1) / TPB, TPB>>>(ei);

    // 2) layer 1: Y1 = X@Wl1^T, Z1 = X@Wr1^T + b1   (concat cols = 256 -> 4 tiles)
    gemm_fused<1><<<dim3((N_NODES + 63) / 64, (2 * D_HID) / 64), TPB>>>(X, Wl1, Wr1, b1);

    // 3) scatter Y1 into AGG1 (one full warp per edge, float4 red)
    scatter_kernel<1><<<(N_EDGES * (D_HID / 4)) / TPB, TPB>>>(ei);

    // 4) H = relu(AGG1/deg + Z1)
    combine_kernel<1><<<(N_NODES * D_HID / 4) / TPB, TPB>>>(nullptr);

    // 5) layer 2: Y2 = H@Wl2^T, Z2 = H@Wr2^T + b2   (concat cols = 128 -> 2 tiles)
    gemm_fused<2><<<dim3((N_NODES + 63) / 64, (2 * D_OUTD) / 64), TPB>>>(X, Wl2, Wr2, b2);

    // 6) scatter Y2 into AGG2 (half warp per edge)
    scatter_kernel<2><<<(N_EDGES * (D_OUTD / 4)) / TPB, TPB>>>(ei);

    // 7) out = AGG2/deg + Z2
    combine_kernel<2><<<(N_NODES * D_OUTD / 4) / TPB, TPB>>>(out);
}

// round 4
// speedup vs baseline: 1.1019x; 1.1019x over previous
#include <cuda_runtime.h>

#define N_NODES 100000
#define N_EDGES 1600000
#define D_IN 128
#define D_HID 128
#define D_OUTD 64

// ---------------- scratch (device globals; no allocation) ----------------
__device__ float g_Y1[N_NODES * D_HID];    // X @ W_l1^T
__device__ float g_Z1[N_NODES * D_HID];    // X @ W_r1^T + b1
__device__ float g_AGG1[N_NODES * D_HID];
__device__ float g_H[N_NODES * D_HID];     // layer-1 output (post relu)
__device__ float g_Y2[N_NODES * D_OUTD];   // H @ W_l2^T
__device__ float g_Z2[N_NODES * D_OUTD];   // H @ W_r2^T + b2
__device__ float g_AGG2[N_NODES * D_OUTD];
__device__ int   g_deg[N_NODES];
__device__ int   g_is64;                   // 1 if edge_index is int64, 0 if int32

// ---------------- dtype probe: int64 indices have zero high words ----------
__global__ void detect_kernel(const int* __restrict__ ei) {
    int all_zero = 1;
    for (int i = 0; i < 128; i++) {
        if (ei[2 * i + 1] != 0) { all_zero = 0; break; }
    }
    g_is64 = all_zero;
}

__device__ __forceinline__ int edge_at(const int* ei, int idx, int is64) {
    return is64 ? (int)((const long long*)ei)[idx] : ei[idx];
}

// ---------------- zero accumulators + degree ----------------
__global__ void zero_kernel() {
    int i = blockIdx.x * blockDim.x + threadIdx.x;
    const float4 z = make_float4(0.f, 0.f, 0.f, 0.f);
    if (i < N_NODES * D_HID / 4)  ((float4*)g_AGG1)[i] = z;
    if (i < N_NODES * D_OUTD / 4) ((float4*)g_AGG2)[i] = z;
    if (i < N_NODES / 4)          ((int4*)g_deg)[i] = make_int4(0, 0, 0, 0);
}

__global__ void deg_kernel(const int* __restrict__ ei) {
    int e = blockIdx.x * blockDim.x + threadIdx.x;
    if (e < N_EDGES) {
        int is64 = g_is64;
        int dst = edge_at(ei, N_EDGES + e, is64);
        if (dst >= 0 && dst < N_NODES) atomicAdd(&g_deg[dst], 1);
    }
}

// ---------------- fused dual GEMM:  Y = X@Wl^T,  Z = X@Wr^T + b ----------------
// C = X[N,128] @ Wcat[2*DOUT,128]^T.  TM=128 x TN=128 block tile, 256 threads,
// 8x8 per-thread micro-tile, TK=16, register double-buffered global loads.
// Concat col c: c < DOUT -> Y (Wl row c); c >= DOUT -> Z (Wr row c-DOUT).
template <int LAYER>
__global__ __launch_bounds__(256) void gemm_fused(const float* __restrict__ Xin,
                                                  const float* __restrict__ Wl,
                                                  const float* __restrict__ Wr,
                                                  const float* __restrict__ bias) {
    constexpr int DOUT = (LAYER == 1) ? D_HID : D_OUTD;
    constexpr int K = 128, TM = 128, TN = 128, TK = 16;

    const float* X = (LAYER == 1) ? Xin : g_H;
    float* Y = (LAYER == 1) ? g_Y1 : g_Y2;
    float* Z = (LAYER == 1) ? g_Z1 : g_Z2;

    __shared__ float Xs[TK][TM];
    __shared__ float Ws[TK][TN];

    const int tid = threadIdx.x;
    const int tx = tid & 15;          // 0..15 -> 8 cols each
    const int ty = tid >> 4;          // 0..15 -> 8 rows each
    const int m0 = blockIdx.x * TM;
    const int n0 = blockIdx.y * TN;   // concat col base

    // loader mapping: 256 threads -> 128 rows x 2 k-halves (8 floats each)
    const int lr = tid >> 1;          // 0..127
    const int lc = tid & 1;           // 0..1
    const int kb = lc * 8;

    int mrow = m0 + lr; if (mrow >= N_NODES) mrow = N_NODES - 1;
    const float* xptr = X + (size_t)mrow * K + kb;

    const int cr = n0 + lr;           // concat row of Wcat
    const float* wrow = (cr < DOUT) ? (Wl + (size_t)cr * K)
                                    : (Wr + (size_t)(cr - DOUT) * K);
    const float* wptr = wrow + kb;

    // prefetch tile 0
    float4 xa = *(const float4*)(xptr);
    float4 xb = *(const float4*)(xptr + 4);
    float4 wa = *(const float4*)(wptr);
    float4 wb = *(const float4*)(wptr + 4);

    float acc[8][8] = {};

    for (int k0 = 0; k0 < K; k0 += TK) {
        __syncthreads();
        Xs[kb + 0][lr] = xa.x; Xs[kb + 1][lr] = xa.y; Xs[kb + 2][lr] = xa.z; Xs[kb + 3][lr] = xa.w;
        Xs[kb + 4][lr] = xb.x; Xs[kb + 5][lr] = xb.y; Xs[kb + 6][lr] = xb.z; Xs[kb + 7][lr] = xb.w;
        Ws[kb + 0][lr] = wa.x; Ws[kb + 1][lr] = wa.y; Ws[kb + 2][lr] = wa.z; Ws[kb + 3][lr] = wa.w;
        Ws[kb + 4][lr] = wb.x; Ws[kb + 5][lr] = wb.y; Ws[kb + 6][lr] = wb.z; Ws[kb + 7][lr] = wb.w;
        __syncthreads();

        if (k0 + TK < K) {   // prefetch next tile into registers
            xa = *(const float4*)(xptr + k0 + TK);
            xb = *(const float4*)(xptr + k0 + TK + 4);
            wa = *(const float4*)(wptr + k0 + TK);
            wb = *(const float4*)(wptr + k0 + TK + 4);
        }

#pragma unroll
        for (int k = 0; k < TK; k++) {
            float4 a0 = *(const float4*)&Xs[k][ty * 8];
            float4 a1 = *(const float4*)&Xs[k][ty * 8 + 4];
            float4 b0 = *(const float4*)&Ws[k][tx * 8];
            float4 b1 = *(const float4*)&Ws[k][tx * 8 + 4];
            float av[8] = {a0.x, a0.y, a0.z, a0.w, a1.x, a1.y, a1.z, a1.w};
            float bv[8] = {b0.x, b0.y, b0.z, b0.w, b1.x, b1.y, b1.z, b1.w};
#pragma unroll
            for (int i = 0; i < 8; i++)
#pragma unroll
                for (int j = 0; j < 8; j++)
                    acc[i][j] = fmaf(av[i], bv[j], acc[i][j]);
        }
    }

    // epilogue: thread's 8 cols lie entirely in Y or entirely in Z
    const int ccol = n0 + tx * 8;
    const bool isZ = (ccol >= DOUT);
    const int col = isZ ? (ccol - DOUT) : ccol;
    float* base = isZ ? Z : Y;

    float bb[8];
#pragma unroll
    for (int j = 0; j < 8; j++) bb[j] = isZ ? bias[col + j] : 0.0f;

#pragma unroll
    for (int i = 0; i < 8; i++) {
        int m = m0 + ty * 8 + i;
        if (m >= N_NODES) continue;
        float* dst = base + (size_t)m * DOUT + col;
        float4 r0 = make_float4(acc[i][0] + bb[0], acc[i][1] + bb[1],
                                acc[i][2] + bb[2], acc[i][3] + bb[3]);
        float4 r1 = make_float4(acc[i][4] + bb[4], acc[i][5] + bb[5],
                                acc[i][6] + bb[6], acc[i][7] + bb[7]);
        *(float4*)(dst)     = r0;
        *(float4*)(dst + 4) = r1;
    }
}

// ---------------- edge scatter: AGG[dst] += Y[src] (vector red atomics) --------
template <int LAYER>
__global__ void scatter_kernel(const int* __restrict__ ei) {
    constexpr int D = (LAYER == 1) ? D_HID : D_OUTD;
    constexpr int G = D / 4;   // lanes per edge (32 or 16)
    const float* Y = (LAYER == 1) ? g_Y1 : g_Y2;
    float* AGG = (LAYER == 1) ? g_AGG1 : g_AGG2;

    int t = blockIdx.x * blockDim.x + threadIdx.x;
    int e = t / G;
    int lane = t % G;
    if (e >= N_EDGES) return;
    int is64 = g_is64;
    int src = edge_at(ei, e, is64);
    int dst = edge_at(ei, N_EDGES + e, is64);
    if ((unsigned)src >= N_NODES || (unsigned)dst >= N_NODES) return;
    float4 v = *(const float4*)(Y + (size_t)src * D + lane * 4);
    float* p = AGG + (size_t)dst * D + lane * 4;
    asm volatile("red.global.add.v4.f32 [%0], {%1, %2, %3, %4};"
                 :: "l"(p), "f"(v.x), "f"(v.y), "f"(v.z), "f"(v.w)
                 : "memory");
}

// ---------------- combine: O = AGG/max(deg,1) + Z  (+relu layer 1) ------------
template <int LAYER>
__global__ void combine_kernel(float* __restrict__ Out) {
    constexpr int D = (LAYER == 1) ? D_HID : D_OUTD;
    constexpr bool RELU = (LAYER == 1);
    const float* AGG = (LAYER == 1) ? g_AGG1 : g_AGG2;
    const float* Z = (LAYER == 1) ? g_Z1 : g_Z2;
    float* O = (LAYER == 1) ? g_H : Out;

    int i = blockIdx.x * blockDim.x + threadIdx.x;   // over N*D/4
    if (i >= N_NODES * D / 4) return;
    int node = i / (D / 4);
    float inv = 1.0f / fmaxf((float)g_deg[node], 1.0f);
    float4 a = ((const float4*)AGG)[i];
    float4 z = ((const float4*)Z)[i];
    float4 r = make_float4(fmaf(a.x, inv, z.x), fmaf(a.y, inv, z.y),
                           fmaf(a.z, inv, z.z), fmaf(a.w, inv, z.w));
    if (RELU) {
        r.x = fmaxf(r.x, 0.f); r.y = fmaxf(r.y, 0.f);
        r.z = fmaxf(r.z, 0.f); r.w = fmaxf(r.w, 0.f);
    }
    ((float4*)O)[i] = r;
}

// ---------------- launch ----------------
extern "C" void kernel_launch(void* const* d_in, const int* in_sizes, int n_in,
                              void* d_out, int out_size) {
    const float* X = nullptr;
    const int*   ei = nullptr;
    const float* Wl1 = nullptr, *Wr1 = nullptr;
    const float* Wl2 = nullptr, *Wr2 = nullptr;
    const float* b1 = nullptr, *b2 = nullptr;

    for (int i = 0; i < n_in; i++) {
        int sz = in_sizes[i];
        const void* p = d_in[i];
        if (sz == N_NODES * D_IN)      X = (const float*)p;
        else if (sz == 2 * N_EDGES)    ei = (const int*)p;
        else if (sz == D_HID * D_IN)   { if (!Wl1) Wl1 = (const float*)p; else Wr1 = (const float*)p; }
        else if (sz == D_OUTD * D_HID) { if (!Wl2) Wl2 = (const float*)p; else Wr2 = (const float*)p; }
        else if (sz == D_HID)          b1 = (const float*)p;
        else if (sz == D_OUTD)         b2 = (const float*)p;
    }
    float* out = (float*)d_out;

    const int TPB = 256;

    detect_kernel<<<1, 1>>>(ei);
    zero_kernel<<<(N_NODES * D_HID / 4 + TPB - 1) / TPB, TPB>>>();
    deg_kernel<<<(N_EDGES + TPB - 1) / TPB, TPB>>>(ei);

    // layer 1: concat cols = 256 -> 2 tiles of 128
    gemm_fused<1><<<dim3((N_NODES + 127) / 128, 2), TPB>>>(X, Wl1, Wr1, b1);
    scatter_kernel<1><<<(N_EDGES * (D_HID / 4)) / TPB, TPB>>>(ei);
    combine_kernel<1><<<(N_NODES * D_HID / 4) / TPB, TPB>>>(nullptr);

    // layer 2: concat cols = 128 -> 1 tile
    gemm_fused<2><<<dim3((N_NODES + 127) / 128, 1), TPB>>>(X, Wl2, Wr2, b2);
    scatter_kernel<2><<<(N_EDGES * (D_OUTD / 4)) / TPB, TPB>>>(ei);
    combine_kernel<2><<<(N_NODES * D_OUTD / 4) / TPB, TPB>>>(out);
}

// round 8
// speedup vs baseline: 1.2221x; 1.1091x over previous
#include <cuda_runtime.h>

#define N_NODES 100000
#define N_EDGES 1600000
#define D_IN 128
#define D_HID 128
#define D_OUTD 64

// ---------------- scratch (device globals; no allocation) ----------------
__device__ float g_Y1[N_NODES * D_HID];    // X @ W_l1^T
__device__ float g_Z1[N_NODES * D_HID];    // X @ W_r1^T + b1
__device__ float g_H[N_NODES * D_HID];     // layer-1 output (post relu)
__device__ float g_Y2[N_NODES * D_OUTD];   // H @ W_l2^T
__device__ float g_Z2[N_NODES * D_OUTD];   // H @ W_r2^T + b2
__device__ int   g_deg[N_NODES];
__device__ int   g_row_ptr[N_NODES + 1];
__device__ int   g_cursor[N_NODES];
__device__ int   g_csr_src[N_EDGES];
__device__ int   g_is64;                   // 1 if edge_index is int64, 0 if int32

// ---------------- dtype probe: int64 indices have zero high words ----------
__global__ void detect_kernel(const int* __restrict__ ei) {
    int all_zero = 1;
    for (int i = 0; i < 128; i++) {
        if (ei[2 * i + 1] != 0) { all_zero = 0; break; }
    }
    g_is64 = all_zero;
}

__device__ __forceinline__ int edge_at(const int* ei, int idx, int is64) {
    return is64 ? (int)((const long long*)ei)[idx] : ei[idx];
}

// ---------------- degree histogram ----------------
__global__ void zero_deg_kernel() {
    int i = blockIdx.x * blockDim.x + threadIdx.x;
    if (i < N_NODES) g_deg[i] = 0;
}

__global__ void deg_kernel(const int* __restrict__ ei) {
    int e = blockIdx.x * blockDim.x + threadIdx.x;
    if (e < N_EDGES) {
        int is64 = g_is64;
        int dst = edge_at(ei, N_EDGES + e, is64);
        if ((unsigned)dst < N_NODES) atomicAdd(&g_deg[dst], 1);
    }
}

// ---------------- exclusive prefix scan (single block, 1024 threads) ----------
__global__ __launch_bounds__(1024) void scan_kernel() {
    constexpr int T = 1024;
    constexpr int CH = (N_NODES + T - 1) / T;   // 98
    __shared__ int sums[T];
    int t = threadIdx.x;
    int beg = t * CH;
    int end = min(beg + CH, N_NODES);
    int s = 0;
    for (int i = beg; i < end; i++) s += g_deg[i];
    sums[t] = s;
    __syncthreads();
    // inclusive scan over per-thread sums
    for (int off = 1; off < T; off <<= 1) {
        int v = (t >= off) ? sums[t - off] : 0;
        __syncthreads();
        sums[t] += v;
        __syncthreads();
    }
    int run = sums[t] - s;   // exclusive prefix for this chunk
    for (int i = beg; i < end; i++) {
        g_row_ptr[i] = run;
        g_cursor[i] = run;
        run += g_deg[i];
    }
    if (t == T - 1) g_row_ptr[N_NODES] = sums[T - 1];
}

// ---------------- CSR fill ----------------
__global__ void fill_kernel(const int* __restrict__ ei) {
    int e = blockIdx.x * blockDim.x + threadIdx.x;
    if (e >= N_EDGES) return;
    int is64 = g_is64;
    int src = edge_at(ei, e, is64);
    int dst = edge_at(ei, N_EDGES + e, is64);
    if ((unsigned)src >= N_NODES || (unsigned)dst >= N_NODES) return;
    int pos = atomicAdd(&g_cursor[dst], 1);
    g_csr_src[pos] = src;
}

// ---------------- fused dual GEMM:  Y = X@Wl^T,  Z = X@Wr^T + b ----------------
// TM=128 x TN=128 block tile, 256 threads, 8x8 micro-tile, TK=16, reg prefetch.
template <int LAYER>
__global__ __launch_bounds__(256) void gemm_fused(const float* __restrict__ Xin,
                                                  const float* __restrict__ Wl,
                                                  const float* __restrict__ Wr,
                                                  const float* __restrict__ bias) {
    constexpr int DOUT = (LAYER == 1) ? D_HID : D_OUTD;
    constexpr int K = 128, TM = 128, TK = 16;

    const float* X = (LAYER == 1) ? Xin : g_H;
    float* Y = (LAYER == 1) ? g_Y1 : g_Y2;
    float* Z = (LAYER == 1) ? g_Z1 : g_Z2;

    __shared__ float Xs[TK][TM];
    __shared__ float Ws[TK][TM];

    const int tid = threadIdx.x;
    const int tx = tid & 15;
    const int ty = tid >> 4;
    const int m0 = blockIdx.x * TM;
    const int n0 = blockIdx.y * TM;   // concat col base

    const int lr = tid >> 1;          // 0..127
    const int lc = tid & 1;
    const int kb = lc * 8;

    int mrow = m0 + lr; if (mrow >= N_NODES) mrow = N_NODES - 1;
    const float* xptr = X + (size_t)mrow * K + kb;

    const int cr = n0 + lr;
    const float* wrow = (cr < DOUT) ? (Wl + (size_t)cr * K)
                                    : (Wr + (size_t)(cr - DOUT) * K);
    const float* wptr = wrow + kb;

    float4 xa = *(const float4*)(xptr);
    float4 xb = *(const float4*)(xptr + 4);
    float4 wa = *(const float4*)(wptr);
    float4 wb = *(const float4*)(wptr + 4);

    float acc[8][8] = {};

    for (int k0 = 0; k0 < K; k0 += TK) {
        __syncthreads();
        Xs[kb + 0][lr] = xa.x; Xs[kb + 1][lr] = xa.y; Xs[kb + 2][lr] = xa.z; Xs[kb + 3][lr] = xa.w;
        Xs[kb + 4][lr] = xb.x; Xs[kb + 5][lr] = xb.y; Xs[kb + 6][lr] = xb.z; Xs[kb + 7][lr] = xb.w;
        Ws[kb + 0][lr] = wa.x; Ws[kb + 1][lr] = wa.y; Ws[kb + 2][lr] = wa.z; Ws[kb + 3][lr] = wa.w;
        Ws[kb + 4][lr] = wb.x; Ws[kb + 5][lr] = wb.y; Ws[kb + 6][lr] = wb.z; Ws[kb + 7][lr] = wb.w;
        __syncthreads();

        if (k0 + TK < K) {
            xa = *(const float4*)(xptr + k0 + TK);
            xb = *(const float4*)(xptr + k0 + TK + 4);
            wa = *(const float4*)(wptr + k0 + TK);
            wb = *(const float4*)(wptr + k0 + TK + 4);
        }

#pragma unroll
        for (int k = 0; k < TK; k++) {
            float4 a0 = *(const float4*)&Xs[k][ty * 8];
            float4 a1 = *(const float4*)&Xs[k][ty * 8 + 4];
            float4 b0 = *(const float4*)&Ws[k][tx * 8];
            float4 b1 = *(const float4*)&Ws[k][tx * 8 + 4];
            float av[8] = {a0.x, a0.y, a0.z, a0.w, a1.x, a1.y, a1.z, a1.w};
            float bv[8] = {b0.x, b0.y, b0.z, b0.w, b1.x, b1.y, b1.z, b1.w};
#pragma unroll
            for (int i = 0; i < 8; i++)
#pragma unroll
                for (int j = 0; j < 8; j++)
                    acc[i][j] = fmaf(av[i], bv[j], acc[i][j]);
        }
    }

    const int ccol = n0 + tx * 8;
    const bool isZ = (ccol >= DOUT);
    const int col = isZ ? (ccol - DOUT) : ccol;
    float* base = isZ ? Z : Y;

    float bb[8];
#pragma unroll
    for (int j = 0; j < 8; j++) bb[j] = isZ ? bias[col + j] : 0.0f;

#pragma unroll
    for (int i = 0; i < 8; i++) {
        int m = m0 + ty * 8 + i;
        if (m >= N_NODES) continue;
        float* dst = base + (size_t)m * DOUT + col;
        float4 r0 = make_float4(acc[i][0] + bb[0], acc[i][1] + bb[1],
                                acc[i][2] + bb[2], acc[i][3] + bb[3]);
        float4 r1 = make_float4(acc[i][4] + bb[4], acc[i][5] + bb[5],
                                acc[i][6] + bb[6], acc[i][7] + bb[7]);
        *(float4*)(dst)     = r0;
        *(float4*)(dst + 4) = r1;
    }
}

// ---------------- warp-per-node gather + mean + Z (+relu) ----------------
// O[i] = act( (1/max(deg,1)) * sum_{s in N(i)} Y[s] + Z[i] )
template <int LAYER>
__global__ __launch_bounds__(256) void agg_kernel(float* __restrict__ OutArg) {
    constexpr int D = (LAYER == 1) ? D_HID : D_OUTD;
    constexpr bool RELU = (LAYER == 1);
    const float* __restrict__ Y = (LAYER == 1) ? g_Y1 : g_Y2;
    const float* __restrict__ Z = (LAYER == 1) ? g_Z1 : g_Z2;
    const int* __restrict__ rp = g_row_ptr;
    const int* __restrict__ cs = g_csr_src;
    float* O = (LAYER == 1) ? g_H : OutArg;

    int warp = (blockIdx.x * blockDim.x + threadIdx.x) >> 5;
    if (warp >= N_NODES) return;
    int lane = threadIdx.x & 31;

    int beg = __ldg(&rp[warp]);
    int end = __ldg(&rp[warp + 1]);
    int deg = end - beg;

    if (D == 128) {
        float4 acc = make_float4(0.f, 0.f, 0.f, 0.f);
        for (int j0 = beg; j0 < end; j0 += 32) {
            int my = (j0 + lane < end) ? __ldg(&cs[j0 + lane]) : 0;
            int cnt = min(32, end - j0);
            for (int t = 0; t < cnt; t++) {
                int s = __shfl_sync(0xffffffffu, my, t);
                float4 v = __ldg((const float4*)(Y + (size_t)s * D + lane * 4));
                acc.x += v.x; acc.y += v.y; acc.z += v.z; acc.w += v.w;
            }
        }
        float inv = 1.0f / fmaxf((float)deg, 1.0f);
        float4 z = __ldg((const float4*)(Z + (size_t)warp * D + lane * 4));
        float4 r = make_float4(fmaf(acc.x, inv, z.x), fmaf(acc.y, inv, z.y),
                               fmaf(acc.z, inv, z.z), fmaf(acc.w, inv, z.w));
        if (RELU) {
            r.x = fmaxf(r.x, 0.f); r.y = fmaxf(r.y, 0.f);
            r.z = fmaxf(r.z, 0.f); r.w = fmaxf(r.w, 0.f);
        }
        *(float4*)(O + (size_t)warp * D + lane * 4) = r;
    } else {
        float2 acc = make_float2(0.f, 0.f);
        for (int j0 = beg; j0 < end; j0 += 32) {
            int my = (j0 + lane < end) ? __ldg(&cs[j0 + lane]) : 0;
            int cnt = min(32, end - j0);
            for (int t = 0; t < cnt; t++) {
                int s = __shfl_sync(0xffffffffu, my, t);
                float2 v = __ldg((const float2*)(Y + (size_t)s * D + lane * 2));
                acc.x += v.x; acc.y += v.y;
            }
        }
        float inv = 1.0f / fmaxf((float)deg, 1.0f);
        float2 z = __ldg((const float2*)(Z + (size_t)warp * D + lane * 2));
        float2 r = make_float2(fmaf(acc.x, inv, z.x), fmaf(acc.y, inv, z.y));
        if (RELU) { r.x = fmaxf(r.x, 0.f); r.y = fmaxf(r.y, 0.f); }
        *(float2*)(O + (size_t)warp * D + lane * 2) = r;
    }
}

// ---------------- launch ----------------
extern "C" void kernel_launch(void* const* d_in, const int* in_sizes, int n_in,
                              void* d_out, int out_size) {
    const float* X = nullptr;
    const int*   ei = nullptr;
    const float* Wl1 = nullptr, *Wr1 = nullptr;
    const float* Wl2 = nullptr, *Wr2 = nullptr;
    const float* b1 = nullptr, *b2 = nullptr;

    for (int i = 0; i < n_in; i++) {
        int sz = in_sizes[i];
        const void* p = d_in[i];
        if (sz == N_NODES * D_IN)      X = (const float*)p;
        else if (sz == 2 * N_EDGES)    ei = (const int*)p;
        else if (sz == D_HID * D_IN)   { if (!Wl1) Wl1 = (const float*)p; else Wr1 = (const float*)p; }
        else if (sz == D_OUTD * D_HID) { if (!Wl2) Wl2 = (const float*)p; else Wr2 = (const float*)p; }
        else if (sz == D_HID)          b1 = (const float*)p;
        else if (sz == D_OUTD)         b2 = (const float*)p;
    }
    float* out = (float*)d_out;

    const int TPB = 256;

    // CSR build (reused by both layers)
    detect_kernel<<<1, 1>>>(ei);
    zero_deg_kernel<<<(N_NODES + TPB - 1) / TPB, TPB>>>();
    deg_kernel<<<(N_EDGES + TPB - 1) / TPB, TPB>>>(ei);
    scan_kernel<<<1, 1024>>>();
    fill_kernel<<<(N_EDGES + TPB - 1) / TPB, TPB>>>(ei);

    // layer 1
    gemm_fused<1><<<dim3((N_NODES + 127) / 128, 2), TPB>>>(X, Wl1, Wr1, b1);
    agg_kernel<1><<<(N_NODES * 32 + TPB - 1) / TPB, TPB>>>(nullptr);

    // layer 2
    gemm_fused<2><<<dim3((N_NODES + 127) / 128, 1), TPB>>>(X, Wl2, Wr2, b2);
    agg_kernel<2><<<(N_NODES * 32 + TPB - 1) / TPB, TPB>>>(out);
}

// round 9
// speedup vs baseline: 1.6918x; 1.3843x over previous
#include <cuda_runtime.h>

#define N_NODES 100000
#define N_EDGES 1600000
#define D_IN 128
#define D_HID 128
#define D_OUTD 64

#define SCAN_B 1024
#define NBLK ((N_NODES + SCAN_B - 1) / SCAN_B)   // 98

// ---------------- scratch (device globals; no allocation) ----------------
__device__ float g_Y1[N_NODES * D_HID];    // X @ W_l1^T
__device__ float g_Z1[N_NODES * D_HID];    // X @ W_r1^T + b1
__device__ float g_H[N_NODES * D_HID];     // layer-1 output (post relu)
__device__ float g_Y2[N_NODES * D_OUTD];   // H @ W_l2^T
__device__ float g_Z2[N_NODES * D_OUTD];   // H @ W_r2^T + b2
__device__ int   g_deg[N_NODES];
__device__ int   g_row_ptr[N_NODES + 1];
__device__ int   g_cursor[N_NODES];
__device__ int   g_csr_src[N_EDGES];
__device__ int   g_blocksum[NBLK];
__device__ int   g_boff[NBLK];
__device__ int   g_total;
__device__ int   g_is64;                   // 1 if edge_index is int64, 0 if int32

// ---------------- dtype probe: int64 indices have zero high words ----------
__global__ void detect_kernel(const int* __restrict__ ei) {
    int all_zero = 1;
    for (int i = 0; i < 128; i++) {
        if (ei[2 * i + 1] != 0) { all_zero = 0; break; }
    }
    g_is64 = all_zero;
}

__device__ __forceinline__ int edge_at(const int* ei, int idx, int is64) {
    return is64 ? (int)((const long long*)ei)[idx] : ei[idx];
}

// ---------------- degree histogram ----------------
__global__ void zero_deg_kernel() {
    int i = blockIdx.x * blockDim.x + threadIdx.x;
    if (i < N_NODES) g_deg[i] = 0;
}

__global__ void deg_kernel(const int* __restrict__ ei) {
    int e = blockIdx.x * blockDim.x + threadIdx.x;
    if (e < N_EDGES) {
        int is64 = g_is64;
        int dst = edge_at(ei, N_EDGES + e, is64);
        if ((unsigned)dst < N_NODES) atomicAdd(&g_deg[dst], 1);
    }
}

// ---------------- 3-phase exclusive scan ----------------
// A: per-block (1024 elts) exclusive scan into g_row_ptr; block total to g_blocksum
__global__ __launch_bounds__(SCAN_B) void scanA_kernel() {
    __shared__ int s[SCAN_B];
    int t = threadIdx.x;
    int i = blockIdx.x * SCAN_B + t;
    int v = (i < N_NODES) ? g_deg[i] : 0;
    s[t] = v;
    __syncthreads();
    for (int off = 1; off < SCAN_B; off <<= 1) {
        int u = (t >= off) ? s[t - off] : 0;
        __syncthreads();
        s[t] += u;
        __syncthreads();
    }
    if (i < N_NODES) g_row_ptr[i] = s[t] - v;     // exclusive within block
    if (t == SCAN_B - 1) g_blocksum[blockIdx.x] = s[t];
}

// B: scan the NBLK block sums (one small block)
__global__ __launch_bounds__(128) void scanB_kernel() {
    __shared__ int s[128];
    int t = threadIdx.x;
    int v = (t < NBLK) ? g_blocksum[t] : 0;
    s[t] = v;
    __syncthreads();
    for (int off = 1; off < 128; off <<= 1) {
        int u = (t >= off) ? s[t - off] : 0;
        __syncthreads();
        s[t] += u;
        __syncthreads();
    }
    if (t < NBLK) g_boff[t] = s[t] - v;           // exclusive block offsets
    if (t == 127) g_total = s[127];
}

// C: add block offsets, init cursor, write sentinel
__global__ __launch_bounds__(SCAN_B) void scanC_kernel() {
    int i = blockIdx.x * SCAN_B + threadIdx.x;
    if (i < N_NODES) {
        int r = g_row_ptr[i] + g_boff[blockIdx.x];
        g_row_ptr[i] = r;
        g_cursor[i] = r;
    }
    if (i == 0) g_row_ptr[N_NODES] = g_total;
}

// ---------------- CSR fill ----------------
__global__ void fill_kernel(const int* __restrict__ ei) {
    int e = blockIdx.x * blockDim.x + threadIdx.x;
    if (e >= N_EDGES) return;
    int is64 = g_is64;
    int src = edge_at(ei, e, is64);
    int dst = edge_at(ei, N_EDGES + e, is64);
    if ((unsigned)src >= N_NODES || (unsigned)dst >= N_NODES) return;
    int pos = atomicAdd(&g_cursor[dst], 1);
    g_csr_src[pos] = src;
}

// ---------------- fused dual GEMM:  Y = X@Wl^T,  Z = X@Wr^T + b ----------------
// TM=128 x TN=128 block tile, 256 threads, 8x8 micro-tile, TK=16, reg prefetch.
template <int LAYER>
__global__ __launch_bounds__(256) void gemm_fused(const float* __restrict__ Xin,
                                                  const float* __restrict__ Wl,
                                                  const float* __restrict__ Wr,
                                                  const float* __restrict__ bias) {
    constexpr int DOUT = (LAYER == 1) ? D_HID : D_OUTD;
    constexpr int K = 128, TM = 128, TK = 16;

    const float* X = (LAYER == 1) ? Xin : g_H;
    float* Y = (LAYER == 1) ? g_Y1 : g_Y2;
    float* Z = (LAYER == 1) ? g_Z1 : g_Z2;

    __shared__ float Xs[TK][TM];
    __shared__ float Ws[TK][TM];

    const int tid = threadIdx.x;
    const int tx = tid & 15;
    const int ty = tid >> 4;
    const int m0 = blockIdx.x * TM;
    const int n0 = blockIdx.y * TM;   // concat col base

    const int lr = tid >> 1;          // 0..127
    const int lc = tid & 1;
    const int kb = lc * 8;

    int mrow = m0 + lr; if (mrow >= N_NODES) mrow = N_NODES - 1;
    const float* xptr = X + (size_t)mrow * K + kb;

    const int cr = n0 + lr;
    const float* wrow = (cr < DOUT) ? (Wl + (size_t)cr * K)
                                    : (Wr + (size_t)(cr - DOUT) * K);
    const float* wptr = wrow + kb;

    float4 xa = *(const float4*)(xptr);
    float4 xb = *(const float4*)(xptr + 4);
    float4 wa = *(const float4*)(wptr);
    float4 wb = *(const float4*)(wptr + 4);

    float acc[8][8] = {};

    for (int k0 = 0; k0 < K; k0 += TK) {
        __syncthreads();
        Xs[kb + 0][lr] = xa.x; Xs[kb + 1][lr] = xa.y; Xs[kb + 2][lr] = xa.z; Xs[kb + 3][lr] = xa.w;
        Xs[kb + 4][lr] = xb.x; Xs[kb + 5][lr] = xb.y; Xs[kb + 6][lr] = xb.z; Xs[kb + 7][lr] = xb.w;
        Ws[kb + 0][lr] = wa.x; Ws[kb + 1][lr] = wa.y; Ws[kb + 2][lr] = wa.z; Ws[kb + 3][lr] = wa.w;
        Ws[kb + 4][lr] = wb.x; Ws[kb + 5][lr] = wb.y; Ws[kb + 6][lr] = wb.z; Ws[kb + 7][lr] = wb.w;
        __syncthreads();

        if (k0 + TK < K) {
            xa = *(const float4*)(xptr + k0 + TK);
            xb = *(const float4*)(xptr + k0 + TK + 4);
            wa = *(const float4*)(wptr + k0 + TK);
            wb = *(const float4*)(wptr + k0 + TK + 4);
        }

#pragma unroll
        for (int k = 0; k < TK; k++) {
            float4 a0 = *(const float4*)&Xs[k][ty * 8];
            float4 a1 = *(const float4*)&Xs[k][ty * 8 + 4];
            float4 b0 = *(const float4*)&Ws[k][tx * 8];
            float4 b1 = *(const float4*)&Ws[k][tx * 8 + 4];
            float av[8] = {a0.x, a0.y, a0.z, a0.w, a1.x, a1.y, a1.z, a1.w};
            float bv[8] = {b0.x, b0.y, b0.z, b0.w, b1.x, b1.y, b1.z, b1.w};
#pragma unroll
            for (int i = 0; i < 8; i++)
#pragma unroll
                for (int j = 0; j < 8; j++)
                    acc[i][j] = fmaf(av[i], bv[j], acc[i][j]);
        }
    }

    const int ccol = n0 + tx * 8;
    const bool isZ = (ccol >= DOUT);
    const int col = isZ ? (ccol - DOUT) : ccol;
    float* base = isZ ? Z : Y;

    float bb[8];
#pragma unroll
    for (int j = 0; j < 8; j++) bb[j] = isZ ? bias[col + j] : 0.0f;

#pragma unroll
    for (int i = 0; i < 8; i++) {
        int m = m0 + ty * 8 + i;
        if (m >= N_NODES) continue;
        float* dst = base + (size_t)m * DOUT + col;
        float4 r0 = make_float4(acc[i][0] + bb[0], acc[i][1] + bb[1],
                                acc[i][2] + bb[2], acc[i][3] + bb[3]);
        float4 r1 = make_float4(acc[i][4] + bb[4], acc[i][5] + bb[5],
                                acc[i][6] + bb[6], acc[i][7] + bb[7]);
        *(float4*)(dst)     = r0;
        *(float4*)(dst + 4) = r1;
    }
}

// ---------------- warp-per-node gather + mean + Z (+relu) ----------------
// O[i] = act( (1/max(deg,1)) * sum_{s in N(i)} Y[s] + Z[i] )
template <int LAYER>
__global__ __launch_bounds__(256) void agg_kernel(float* __restrict__ OutArg) {
    constexpr int D = (LAYER == 1) ? D_HID : D_OUTD;
    constexpr bool RELU = (LAYER == 1);
    const float* __restrict__ Y = (LAYER == 1) ? g_Y1 : g_Y2;
    const float* __restrict__ Z = (LAYER == 1) ? g_Z1 : g_Z2;
    const int* __restrict__ rp = g_row_ptr;
    const int* __restrict__ cs = g_csr_src;
    float* O = (LAYER == 1) ? g_H : OutArg;

    int warp = (blockIdx.x * blockDim.x + threadIdx.x) >> 5;
    if (warp >= N_NODES) return;
    int lane = threadIdx.x & 31;

    int beg = __ldg(&rp[warp]);
    int end = __ldg(&rp[warp + 1]);
    int deg = end - beg;

    if (D == 128) {
        float4 acc = make_float4(0.f, 0.f, 0.f, 0.f);
        for (int j0 = beg; j0 < end; j0 += 32) {
            int my = (j0 + lane < end) ? __ldg(&cs[j0 + lane]) : 0;
            int cnt = min(32, end - j0);
            for (int t = 0; t < cnt; t++) {
                int s = __shfl_sync(0xffffffffu, my, t);
                float4 v = __ldg((const float4*)(Y + (size_t)s * D + lane * 4));
                acc.x += v.x; acc.y += v.y; acc.z += v.z; acc.w += v.w;
            }
        }
        float inv = 1.0f / fmaxf((float)deg, 1.0f);
        float4 z = __ldg((const float4*)(Z + (size_t)warp * D + lane * 4));
        float4 r = make_float4(fmaf(acc.x, inv, z.x), fmaf(acc.y, inv, z.y),
                               fmaf(acc.z, inv, z.z), fmaf(acc.w, inv, z.w));
        if (RELU) {
            r.x = fmaxf(r.x, 0.f); r.y = fmaxf(r.y, 0.f);
            r.z = fmaxf(r.z, 0.f); r.w = fmaxf(r.w, 0.f);
        }
        *(float4*)(O + (size_t)warp * D + lane * 4) = r;
    } else {
        float2 acc = make_float2(0.f, 0.f);
        for (int j0 = beg; j0 < end; j0 += 32) {
            int my = (j0 + lane < end) ? __ldg(&cs[j0 + lane]) : 0;
            int cnt = min(32, end - j0);
            for (int t = 0; t < cnt; t++) {
                int s = __shfl_sync(0xffffffffu, my, t);
                float2 v = __ldg((const float2*)(Y + (size_t)s * D + lane * 2));
                acc.x += v.x; acc.y += v.y;
            }
        }
        float inv = 1.0f / fmaxf((float)deg, 1.0f);
        float2 z = __ldg((const float2*)(Z + (size_t)warp * D + lane * 2));
        float2 r = make_float2(fmaf(acc.x, inv, z.x), fmaf(acc.y, inv, z.y));
        if (RELU) { r.x = fmaxf(r.x, 0.f); r.y = fmaxf(r.y, 0.f); }
        *(float2*)(O + (size_t)warp * D + lane * 2) = r;
    }
}

// ---------------- launch ----------------
extern "C" void kernel_launch(void* const* d_in, const int* in_sizes, int n_in,
                              void* d_out, int out_size) {
    const float* X = nullptr;
    const int*   ei = nullptr;
    const float* Wl1 = nullptr, *Wr1 = nullptr;
    const float* Wl2 = nullptr, *Wr2 = nullptr;
    const float* b1 = nullptr, *b2 = nullptr;

    for (int i = 0; i < n_in; i++) {
        int sz = in_sizes[i];
        const void* p = d_in[i];
        if (sz == N_NODES * D_IN)      X = (const float*)p;
        else if (sz == 2 * N_EDGES)    ei = (const int*)p;
        else if (sz == D_HID * D_IN)   { if (!Wl1) Wl1 = (const float*)p; else Wr1 = (const float*)p; }
        else if (sz == D_OUTD * D_HID) { if (!Wl2) Wl2 = (const float*)p; else Wr2 = (const float*)p; }
        else if (sz == D_HID)          b1 = (const float*)p;
        else if (sz == D_OUTD)         b2 = (const float*)p;
    }
    float* out = (float*)d_out;

    const int TPB = 256;

    // CSR build (reused by both layers)
    detect_kernel<<<1, 1>>>(ei);
    zero_deg_kernel<<<(N_NODES + TPB - 1) / TPB, TPB>>>();
    deg_kernel<<<(N_EDGES + TPB - 1) / TPB, TPB>>>(ei);
    scanA_kernel<<<NBLK, SCAN_B>>>();
    scanB_kernel<<<1, 128>>>();
    scanC_kernel<<<NBLK, SCAN_B>>>();
    fill_kernel<<<(N_EDGES + TPB - 1) / TPB, TPB>>>(ei);

    // layer 1
    gemm_fused<1><<<dim3((N_NODES + 127) / 128, 2), TPB>>>(X, Wl1, Wr1, b1);
    agg_kernel<1><<<(N_NODES * 32 + TPB - 1) / TPB, TPB>>>(nullptr);

    // layer 2
    gemm_fused<2><<<dim3((N_NODES + 127) / 128, 1), TPB>>>(X, Wl2, Wr2, b2);
    agg_kernel<2><<<(N_NODES * 32 + TPB - 1) / TPB, TPB>>>(out);
}